// round 10
// baseline (speedup 1.0000x reference)
#include <cuda_runtime.h>

// Range_Fourier_Net: y = DFT_512(x) per row, complex, output stacked (re, im).
// Radix-8^3 FFT, exact twiddles generated from row 1 of the DFT weight matrix.
//
// R10 = R8 (2 rows per 64-thread group, paired-float2 conflict-free smem
// exchanges, 3 named group barriers) + __launch_bounds__(256,4).
// R8's natural reg use is 56 < the 64-reg 4-CTA ceiling, so unlike R7 this
// raises residency (3->4 CTAs/SM, 24->32 warps) without spilling.

#define GROUPS 4
#define CTA_THREADS (GROUPS * 64)
#define BUF_LEN 576   // >= 7*72+63+1 = 568 and >= 7*66+63+1 = 526

__device__ __forceinline__ float2 cadd(float2 a, float2 b) {
    return make_float2(a.x + b.x, a.y + b.y);
}
__device__ __forceinline__ float2 csub(float2 a, float2 b) {
    return make_float2(a.x - b.x, a.y - b.y);
}
__device__ __forceinline__ float2 cmul(float2 a, float2 b) {
    return make_float2(fmaf(a.x, b.x, -a.y * b.y), fmaf(a.x, b.y, a.y * b.x));
}
// multiply by -i  (W8^2)
__device__ __forceinline__ float2 mul_mi(float2 a) { return make_float2(a.y, -a.x); }

// Natural-order 8-point DFT: v[h] = sum_j v_in[j] * W8^{j*h}, W8 = exp(-i*pi/4)
__device__ __forceinline__ void dft8(float2 v[8]) {
    float2 e0 = v[0], e1 = v[2], e2 = v[4], e3 = v[6];
    float2 o0 = v[1], o1 = v[3], o2 = v[5], o3 = v[7];
    float2 t0 = cadd(e0, e2), t1 = csub(e0, e2);
    float2 t2 = cadd(e1, e3), t3 = mul_mi(csub(e1, e3));
    float2 E0 = cadd(t0, t2), E2 = csub(t0, t2);
    float2 E1 = cadd(t1, t3), E3 = csub(t1, t3);
    float2 s0 = cadd(o0, o2), s1 = csub(o0, o2);
    float2 s2 = cadd(o1, o3), s3 = mul_mi(csub(o1, o3));
    float2 O0 = cadd(s0, s2), O2 = csub(s0, s2);
    float2 O1 = cadd(s1, s3), O3 = csub(s1, s3);
    const float S = 0.70710678118654752440f;
    float2 W1 = make_float2(S * (O1.x + O1.y), S * (O1.y - O1.x));
    float2 W2 = mul_mi(O2);
    float2 W3 = make_float2(S * (O3.y - O3.x), -S * (O3.x + O3.y));
    v[0] = cadd(E0, O0); v[4] = csub(E0, O0);
    v[1] = cadd(E1, W1); v[5] = csub(E1, W1);
    v[2] = cadd(E2, W2); v[6] = csub(E2, W2);
    v[3] = cadd(E3, W3); v[7] = csub(E3, W3);
}

__device__ __forceinline__ void group_bar(int grp) {
    asm volatile("bar.sync %0, 64;" :: "r"(grp + 1) : "memory");
}

// twiddle chain: v[h] *= base^h for h = 1..7
__device__ __forceinline__ void twiddle_chain(float2 v[8], float2 base) {
    float2 f = base;
    #pragma unroll
    for (int h = 1; h < 8; h++) {
        v[h] = cmul(v[h], f);
        if (h < 7) f = cmul(f, base);
    }
}

__global__ __launch_bounds__(CTA_THREADS, 4)
void fft512_kernel(const float* __restrict__ xre, const float* __restrict__ xim,
                   const float* __restrict__ wre, const float* __restrict__ wim,
                   float2* __restrict__ out, int nrows)
{
    // paired buffers: element = (rowA value, rowB value)
    __shared__ float2 bufRe[GROUPS][BUF_LEN];
    __shared__ float2 bufIm[GROUPS][BUF_LEN];

    const int tid = threadIdx.x;
    const int grp = tid >> 6;      // group within CTA
    const int t   = tid & 63;      // 0..63
    const int j0  = t & 7;
    const int h2s = t >> 3;
    const int rowA = (blockIdx.x * GROUPS + grp) * 2;
    const int rowB = rowA + 1;
    const bool actA = rowA < nrows;
    const bool actB = rowB < nrows;

    // Per-thread exact base twiddles from DFT-matrix row 1: W512^m = w[512+m]
    const float2 base1 = make_float2(__ldg(&wre[512 + t]),      __ldg(&wim[512 + t]));
    const float2 base2 = make_float2(__ldg(&wre[512 + 8 * j0]), __ldg(&wim[512 + 8 * j0]));

    // ---- front-batched loads: 32 LDGs in flight ----
    float2 a[8], b[8];
    {
        const float* xrA = xre + (size_t)rowA * 512;
        const float* xiA = xim + (size_t)rowA * 512;
        const float* xrB = xre + (size_t)rowB * 512;
        const float* xiB = xim + (size_t)rowB * 512;
        float arv[8], aiv[8], brv[8], biv[8];
        #pragma unroll
        for (int j = 0; j < 8; j++) arv[j] = actA ? xrA[t + 64 * j] : 0.f;
        #pragma unroll
        for (int j = 0; j < 8; j++) aiv[j] = actA ? xiA[t + 64 * j] : 0.f;
        #pragma unroll
        for (int j = 0; j < 8; j++) brv[j] = actB ? xrB[t + 64 * j] : 0.f;
        #pragma unroll
        for (int j = 0; j < 8; j++) biv[j] = actB ? xiB[t + 64 * j] : 0.f;
        #pragma unroll
        for (int j = 0; j < 8; j++) { a[j] = make_float2(arv[j], aiv[j]);
                                      b[j] = make_float2(brv[j], biv[j]); }
    }

    // ---- Stage 1 (both rows): radix-8 over j2, twiddle (W^t)^h2 ----
    dft8(a); twiddle_chain(a, base1);
    dft8(b); twiddle_chain(b, base1);

    // exchange 1 store: pitch 72, STS.64 (words 16h+2t: conflict-free)
    #pragma unroll
    for (int h = 0; h < 8; h++) {
        int p = h * 72 + t;
        bufRe[grp][p] = make_float2(a[h].x, b[h].x);
        bufIm[grp][p] = make_float2(a[h].y, b[h].y);
    }
    group_bar(grp);

    // ---- Stage 2 (both rows): radix-8 over j1, twiddle (W^(8*j0))^h1 ----
    #pragma unroll
    for (int j1 = 0; j1 < 8; j1++) {
        int p = h2s * 72 + j1 * 8 + j0;
        float2 re = bufRe[grp][p];
        float2 im = bufIm[grp][p];
        a[j1] = make_float2(re.x, im.x);
        b[j1] = make_float2(re.y, im.y);
    }
    dft8(a); twiddle_chain(a, base2);
    dft8(b); twiddle_chain(b, base2);

    group_bar(grp);   // all exchange-1 reads done before overwrite

    // exchange 2 store: pitch 66 (words 4*j0+16h+2h2: conflict-free for .64)
    #pragma unroll
    for (int h = 0; h < 8; h++) {
        int p = j0 * 66 + h * 8 + h2s;
        bufRe[grp][p] = make_float2(a[h].x, b[h].x);
        bufIm[grp][p] = make_float2(a[h].y, b[h].y);
    }
    group_bar(grp);

    // ---- Stage 3 (both rows): radix-8 over j0; output h = h0*64 + t ----
    #pragma unroll
    for (int j = 0; j < 8; j++) {
        int p = j * 66 + t;
        float2 re = bufRe[grp][p];
        float2 im = bufIm[grp][p];
        a[j] = make_float2(re.x, im.x);
        b[j] = make_float2(re.y, im.y);
    }
    dft8(a);
    dft8(b);

    if (actA) {
        float2* orow = out + (size_t)rowA * 512;
        #pragma unroll
        for (int h0 = 0; h0 < 8; h0++) orow[h0 * 64 + t] = a[h0];
    }
    if (actB) {
        float2* orow = out + (size_t)rowB * 512;
        #pragma unroll
        for (int h0 = 0; h0 < 8; h0++) orow[h0 * 64 + t] = b[h0];
    }
}

extern "C" void kernel_launch(void* const* d_in, const int* in_sizes, int n_in,
                              void* d_out, int out_size)
{
    const float* xre = (const float*)d_in[0];
    const float* xim = (const float*)d_in[1];
    const float* wre = (const float*)d_in[2];
    const float* wim = (const float*)d_in[3];
    float2* out = (float2*)d_out;

    // Ask for the max shared-memory carveout so 4 CTAs (147.6 KB) fit per SM.
    // Host-side attribute set, no allocation, graph-capture safe.
    static bool carveout_done = false;
    if (!carveout_done) {
        cudaFuncSetAttribute(fft512_kernel,
                             cudaFuncAttributePreferredSharedMemoryCarveout, 100);
        carveout_done = true;
    }

    const int nrows = in_sizes[0] / 512;            // 32768
    const int rows_per_cta = GROUPS * 2;            // 8
    const int grid = (nrows + rows_per_cta - 1) / rows_per_cta;   // 4096
    fft512_kernel<<<grid, CTA_THREADS>>>(xre, xim, wre, wim, out, nrows);
}

// round 11
// speedup vs baseline: 1.1148x; 1.1148x over previous
#include <cuda_runtime.h>

// Range_Fourier_Net: y = DFT_512(x) per row, complex, output stacked (re, im).
// Radix-8^3 FFT, exact twiddles generated from row 1 of the DFT weight matrix.
//
// R11 = R8 compute core (2 rows per 64-thread group, paired-float2
// conflict-free smem exchanges, 3 named group barriers) wrapped in a
// grid-stride loop with REGISTER PREFETCH: each iteration first issues the
// next tile's 32 guarded LDGs into a spare register set, then computes the
// current tile. Loads get a full compute phase to complete -> DRAM latency
// fully hidden even at modest occupancy. launch_bounds(256,2) = 128-reg
// ceiling so the ~96-reg working set is never squeezed (R7 lesson).
// No carveout attribute (R10 regression).

#define GROUPS 4
#define CTA_THREADS (GROUPS * 64)
#define GRID_CTAS 592                    // 4 per SM x 148 SMs
#define ROW_STRIDE (GRID_CTAS * GROUPS * 2)   // 4736 rows per sweep
#define BUF_LEN 576   // >= 7*72+63+1 = 568 and >= 7*66+63+1 = 526

__device__ __forceinline__ float2 cadd(float2 a, float2 b) {
    return make_float2(a.x + b.x, a.y + b.y);
}
__device__ __forceinline__ float2 csub(float2 a, float2 b) {
    return make_float2(a.x - b.x, a.y - b.y);
}
__device__ __forceinline__ float2 cmul(float2 a, float2 b) {
    return make_float2(fmaf(a.x, b.x, -a.y * b.y), fmaf(a.x, b.y, a.y * b.x));
}
// multiply by -i  (W8^2)
__device__ __forceinline__ float2 mul_mi(float2 a) { return make_float2(a.y, -a.x); }

// Natural-order 8-point DFT: v[h] = sum_j v_in[j] * W8^{j*h}, W8 = exp(-i*pi/4)
__device__ __forceinline__ void dft8(float2 v[8]) {
    float2 e0 = v[0], e1 = v[2], e2 = v[4], e3 = v[6];
    float2 o0 = v[1], o1 = v[3], o2 = v[5], o3 = v[7];
    float2 t0 = cadd(e0, e2), t1 = csub(e0, e2);
    float2 t2 = cadd(e1, e3), t3 = mul_mi(csub(e1, e3));
    float2 E0 = cadd(t0, t2), E2 = csub(t0, t2);
    float2 E1 = cadd(t1, t3), E3 = csub(t1, t3);
    float2 s0 = cadd(o0, o2), s1 = csub(o0, o2);
    float2 s2 = cadd(o1, o3), s3 = mul_mi(csub(o1, o3));
    float2 O0 = cadd(s0, s2), O2 = csub(s0, s2);
    float2 O1 = cadd(s1, s3), O3 = csub(s1, s3);
    const float S = 0.70710678118654752440f;
    float2 W1 = make_float2(S * (O1.x + O1.y), S * (O1.y - O1.x));
    float2 W2 = mul_mi(O2);
    float2 W3 = make_float2(S * (O3.y - O3.x), -S * (O3.x + O3.y));
    v[0] = cadd(E0, O0); v[4] = csub(E0, O0);
    v[1] = cadd(E1, W1); v[5] = csub(E1, W1);
    v[2] = cadd(E2, W2); v[6] = csub(E2, W2);
    v[3] = cadd(E3, W3); v[7] = csub(E3, W3);
}

__device__ __forceinline__ void group_bar(int grp) {
    asm volatile("bar.sync %0, 64;" :: "r"(grp + 1) : "memory");
}

// twiddle chain: v[h] *= base^h for h = 1..7
__device__ __forceinline__ void twiddle_chain(float2 v[8], float2 base) {
    float2 f = base;
    #pragma unroll
    for (int h = 1; h < 8; h++) {
        v[h] = cmul(v[h], f);
        if (h < 7) f = cmul(f, base);
    }
}

// guarded front-batched load of one row-pair (rowA, rowA+1)
__device__ __forceinline__ void load_pair(
    const float* __restrict__ xre, const float* __restrict__ xim,
    int rowA, int nrows, int t,
    float ar[8], float ai[8], float br[8], float bi[8])
{
    const bool actA = rowA < nrows;
    const bool actB = rowA + 1 < nrows;
    const float* xrA = xre + (size_t)rowA * 512;
    const float* xiA = xim + (size_t)rowA * 512;
    const float* xrB = xrA + 512;
    const float* xiB = xiA + 512;
    #pragma unroll
    for (int j = 0; j < 8; j++) ar[j] = actA ? xrA[t + 64 * j] : 0.f;
    #pragma unroll
    for (int j = 0; j < 8; j++) ai[j] = actA ? xiA[t + 64 * j] : 0.f;
    #pragma unroll
    for (int j = 0; j < 8; j++) br[j] = actB ? xrB[t + 64 * j] : 0.f;
    #pragma unroll
    for (int j = 0; j < 8; j++) bi[j] = actB ? xiB[t + 64 * j] : 0.f;
}

__global__ __launch_bounds__(CTA_THREADS, 2)
void fft512_kernel(const float* __restrict__ xre, const float* __restrict__ xim,
                   const float* __restrict__ wre, const float* __restrict__ wim,
                   float2* __restrict__ out, int nrows)
{
    // paired buffers: element = (rowA value, rowB value)
    __shared__ float2 bufRe[GROUPS][BUF_LEN];
    __shared__ float2 bufIm[GROUPS][BUF_LEN];

    const int tid = threadIdx.x;
    const int grp = tid >> 6;      // group within CTA
    const int t   = tid & 63;      // 0..63
    const int j0  = t & 7;
    const int h2s = t >> 3;

    // Per-thread exact base twiddles from DFT-matrix row 1: W512^m = w[512+m]
    const float2 base1 = make_float2(__ldg(&wre[512 + t]),      __ldg(&wim[512 + t]));
    const float2 base2 = make_float2(__ldg(&wre[512 + 8 * j0]), __ldg(&wim[512 + 8 * j0]));

    int rowA = (blockIdx.x * GROUPS + grp) * 2;

    // prefetch first tile
    float car[8], cai[8], cbr[8], cbi[8];
    load_pair(xre, xim, rowA, nrows, t, car, cai, cbr, cbi);

    #pragma unroll 1
    for (; rowA < nrows; ) {
        const int rowN = rowA + ROW_STRIDE;

        // ---- issue next tile's loads FIRST (hidden behind this tile's compute) ----
        float nar[8], nai[8], nbr[8], nbi[8];
        load_pair(xre, xim, rowN, nrows, t, nar, nai, nbr, nbi);

        // ---- compute current tile ----
        float2 a[8], b[8];
        #pragma unroll
        for (int j = 0; j < 8; j++) { a[j] = make_float2(car[j], cai[j]);
                                      b[j] = make_float2(cbr[j], cbi[j]); }

        // Stage 1 (both rows): radix-8 over j2, twiddle (W^t)^h2
        dft8(a); twiddle_chain(a, base1);
        dft8(b); twiddle_chain(b, base1);

        // exchange 1 store: pitch 72, STS.64 (words 16h+2t: conflict-free)
        #pragma unroll
        for (int h = 0; h < 8; h++) {
            int p = h * 72 + t;
            bufRe[grp][p] = make_float2(a[h].x, b[h].x);
            bufIm[grp][p] = make_float2(a[h].y, b[h].y);
        }
        group_bar(grp);

        // Stage 2 (both rows): radix-8 over j1, twiddle (W^(8*j0))^h1
        #pragma unroll
        for (int j1 = 0; j1 < 8; j1++) {
            int p = h2s * 72 + j1 * 8 + j0;
            float2 re = bufRe[grp][p];
            float2 im = bufIm[grp][p];
            a[j1] = make_float2(re.x, im.x);
            b[j1] = make_float2(re.y, im.y);
        }
        dft8(a); twiddle_chain(a, base2);
        dft8(b); twiddle_chain(b, base2);

        group_bar(grp);   // all exchange-1 reads done before overwrite

        // exchange 2 store: pitch 66 (words 4*j0+16h+2h2: conflict-free .64)
        #pragma unroll
        for (int h = 0; h < 8; h++) {
            int p = j0 * 66 + h * 8 + h2s;
            bufRe[grp][p] = make_float2(a[h].x, b[h].x);
            bufIm[grp][p] = make_float2(a[h].y, b[h].y);
        }
        group_bar(grp);

        // Stage 3 (both rows): radix-8 over j0; output h = h0*64 + t
        #pragma unroll
        for (int j = 0; j < 8; j++) {
            int p = j * 66 + t;
            float2 re = bufRe[grp][p];
            float2 im = bufIm[grp][p];
            a[j] = make_float2(re.x, im.x);
            b[j] = make_float2(re.y, im.y);
        }
        dft8(a);
        dft8(b);

        if (rowA < nrows) {
            float2* orow = out + (size_t)rowA * 512;
            #pragma unroll
            for (int h0 = 0; h0 < 8; h0++) orow[h0 * 64 + t] = a[h0];
        }
        if (rowA + 1 < nrows) {
            float2* orow = out + (size_t)(rowA + 1) * 512;
            #pragma unroll
            for (int h0 = 0; h0 < 8; h0++) orow[h0 * 64 + t] = b[h0];
        }

        group_bar(grp);   // exchange buffers free for next iteration

        // rotate prefetched registers into current
        #pragma unroll
        for (int j = 0; j < 8; j++) { car[j] = nar[j]; cai[j] = nai[j];
                                      cbr[j] = nbr[j]; cbi[j] = nbi[j]; }
        rowA = rowN;
    }
}

extern "C" void kernel_launch(void* const* d_in, const int* in_sizes, int n_in,
                              void* d_out, int out_size)
{
    const float* xre = (const float*)d_in[0];
    const float* xim = (const float*)d_in[1];
    const float* wre = (const float*)d_in[2];
    const float* wim = (const float*)d_in[3];
    float2* out = (float2*)d_out;

    const int nrows = in_sizes[0] / 512;            // 32768
    fft512_kernel<<<GRID_CTAS, CTA_THREADS>>>(xre, xim, wre, wim, out, nrows);
}

// round 12
// speedup vs baseline: 1.1354x; 1.0184x over previous
#include <cuda_runtime.h>

// Range_Fourier_Net: y = DFT_512(x) per row, complex, output stacked (re, im).
// Radix-8^3 FFT, exact twiddles generated from row 1 of the DFT weight matrix.
//
// R12: WARP-AUTONOMOUS. One warp = one row pair; each thread owns columns
// t and t+32 (two radix-8 butterflies per stage per row). Both exchanges are
// intra-warp: float4-packed smem scratch (Are,Aim,Bre,Bim) with STS.128 /
// LDS.128, __syncwarp() only — ZERO bar.sync. Pitches 64 (ex1) and 65 (ex2)
// are conflict-free for 128-bit accesses (8-lane phases). 64 front-batched
// LDGs per thread-warp = 4 KB in flight per warp.

#define WARPS_PER_CTA 4
#define CTA_THREADS (WARPS_PER_CTA * 32)
#define P1 64
#define P2 65
#define BUF_LEN 520   // max(7*64+63, 7*65+63)+1 = 519+1

__device__ __forceinline__ float2 cadd(float2 a, float2 b) {
    return make_float2(a.x + b.x, a.y + b.y);
}
__device__ __forceinline__ float2 csub(float2 a, float2 b) {
    return make_float2(a.x - b.x, a.y - b.y);
}
__device__ __forceinline__ float2 cmul(float2 a, float2 b) {
    return make_float2(fmaf(a.x, b.x, -a.y * b.y), fmaf(a.x, b.y, a.y * b.x));
}
// multiply by -i  (W8^2)
__device__ __forceinline__ float2 mul_mi(float2 a) { return make_float2(a.y, -a.x); }

// Natural-order 8-point DFT: v[h] = sum_j v_in[j] * W8^{j*h}, W8 = exp(-i*pi/4)
__device__ __forceinline__ void dft8(float2 v[8]) {
    float2 e0 = v[0], e1 = v[2], e2 = v[4], e3 = v[6];
    float2 o0 = v[1], o1 = v[3], o2 = v[5], o3 = v[7];
    float2 t0 = cadd(e0, e2), t1 = csub(e0, e2);
    float2 t2 = cadd(e1, e3), t3 = mul_mi(csub(e1, e3));
    float2 E0 = cadd(t0, t2), E2 = csub(t0, t2);
    float2 E1 = cadd(t1, t3), E3 = csub(t1, t3);
    float2 s0 = cadd(o0, o2), s1 = csub(o0, o2);
    float2 s2 = cadd(o1, o3), s3 = mul_mi(csub(o1, o3));
    float2 O0 = cadd(s0, s2), O2 = csub(s0, s2);
    float2 O1 = cadd(s1, s3), O3 = csub(s1, s3);
    const float S = 0.70710678118654752440f;
    float2 W1 = make_float2(S * (O1.x + O1.y), S * (O1.y - O1.x));
    float2 W2 = mul_mi(O2);
    float2 W3 = make_float2(S * (O3.y - O3.x), -S * (O3.x + O3.y));
    v[0] = cadd(E0, O0); v[4] = csub(E0, O0);
    v[1] = cadd(E1, W1); v[5] = csub(E1, W1);
    v[2] = cadd(E2, W2); v[6] = csub(E2, W2);
    v[3] = cadd(E3, W3); v[7] = csub(E3, W3);
}

// apply base^h (h=1..7) to TWO arrays sharing the same twiddle base
__device__ __forceinline__ void twiddle_chain2(float2 u[8], float2 v[8], float2 base) {
    float2 f = base;
    #pragma unroll
    for (int h = 1; h < 8; h++) {
        u[h] = cmul(u[h], f);
        v[h] = cmul(v[h], f);
        if (h < 7) f = cmul(f, base);
    }
}

__global__ __launch_bounds__(CTA_THREADS, 4)
void fft512_kernel(const float* __restrict__ xre, const float* __restrict__ xim,
                   const float* __restrict__ wre, const float* __restrict__ wim,
                   float2* __restrict__ out, int nrows)
{
    // per warp: one float4 scratch; element = (Are, Aim, Bre, Bim)
    __shared__ float4 buf[WARPS_PER_CTA][BUF_LEN];   // 4*520*16 = 33,280 B

    const int tid  = threadIdx.x;
    const int wid  = tid >> 5;
    const int lane = tid & 31;
    const int c0 = lane;            // column set 0
    const int c1 = lane + 32;       // column set 1
    const int j0 = lane & 7;        // shared by c0 and c1 (mod 8 equal)
    const int q0 = lane >> 3;       // c0 >> 3
    const int q1 = q0 + 4;          // c1 >> 3

    const int rowA = (blockIdx.x * WARPS_PER_CTA + wid) * 2;
    const int rowB = rowA + 1;
    const bool actA = rowA < nrows;
    const bool actB = rowB < nrows;

    // exact base twiddles from DFT-matrix row 1: W512^m = w[512+m]
    const float2 base1a = make_float2(__ldg(&wre[512 + c0]), __ldg(&wim[512 + c0]));
    const float2 base1b = make_float2(__ldg(&wre[512 + c1]), __ldg(&wim[512 + c1]));
    const float2 base2  = make_float2(__ldg(&wre[512 + 8 * j0]), __ldg(&wim[512 + 8 * j0]));

    // ---- front-batched loads: 64 LDGs (4 KB) in flight per thread ----
    float2 a0[8], a1[8], b0[8], b1[8];
    {
        const float* xrA = xre + (size_t)rowA * 512;
        const float* xiA = xim + (size_t)rowA * 512;
        const float* xrB = xrA + 512;
        const float* xiB = xiA + 512;
        float a0r[8], a0i[8], a1r[8], a1i[8];
        float b0r[8], b0i[8], b1r[8], b1i[8];
        #pragma unroll
        for (int j = 0; j < 8; j++) a0r[j] = actA ? xrA[c0 + 64 * j] : 0.f;
        #pragma unroll
        for (int j = 0; j < 8; j++) a1r[j] = actA ? xrA[c1 + 64 * j] : 0.f;
        #pragma unroll
        for (int j = 0; j < 8; j++) a0i[j] = actA ? xiA[c0 + 64 * j] : 0.f;
        #pragma unroll
        for (int j = 0; j < 8; j++) a1i[j] = actA ? xiA[c1 + 64 * j] : 0.f;
        #pragma unroll
        for (int j = 0; j < 8; j++) b0r[j] = actB ? xrB[c0 + 64 * j] : 0.f;
        #pragma unroll
        for (int j = 0; j < 8; j++) b1r[j] = actB ? xrB[c1 + 64 * j] : 0.f;
        #pragma unroll
        for (int j = 0; j < 8; j++) b0i[j] = actB ? xiB[c0 + 64 * j] : 0.f;
        #pragma unroll
        for (int j = 0; j < 8; j++) b1i[j] = actB ? xiB[c1 + 64 * j] : 0.f;
        #pragma unroll
        for (int j = 0; j < 8; j++) {
            a0[j] = make_float2(a0r[j], a0i[j]);
            a1[j] = make_float2(a1r[j], a1i[j]);
            b0[j] = make_float2(b0r[j], b0i[j]);
            b1[j] = make_float2(b1r[j], b1i[j]);
        }
    }

    // ---- Stage 1: radix-8 over j2 (stride 64); twiddle (W^c)^h2 ----
    dft8(a0); dft8(b0); twiddle_chain2(a0, b0, base1a);
    dft8(a1); dft8(b1); twiddle_chain2(a1, b1, base1b);

    // exchange 1 store: p = h*64 + c  (STS.128, conflict-free)
    #pragma unroll
    for (int h = 0; h < 8; h++) {
        buf[wid][h * P1 + c0] = make_float4(a0[h].x, a0[h].y, b0[h].x, b0[h].y);
        buf[wid][h * P1 + c1] = make_float4(a1[h].x, a1[h].y, b1[h].x, b1[h].y);
    }
    __syncwarp();

    // exchange 1 gather: column c == (q, j0) reads p = q*64 + j1*8 + j0
    #pragma unroll
    for (int j1 = 0; j1 < 8; j1++) {
        float4 u = buf[wid][q0 * P1 + j1 * 8 + j0];
        float4 v = buf[wid][q1 * P1 + j1 * 8 + j0];
        a0[j1] = make_float2(u.x, u.y);  b0[j1] = make_float2(u.z, u.w);
        a1[j1] = make_float2(v.x, v.y);  b1[j1] = make_float2(v.z, v.w);
    }
    __syncwarp();   // all reads done before ex2 overwrites

    // ---- Stage 2: radix-8 over j1; twiddle (W^(8*j0))^h1 (same base, 4 arrays) ----
    dft8(a0); dft8(b0); twiddle_chain2(a0, b0, base2);
    dft8(a1); dft8(b1); twiddle_chain2(a1, b1, base2);

    // exchange 2 store: value h1 of column (q, j0) -> p = j0*65 + h1*8 + q
    #pragma unroll
    for (int h = 0; h < 8; h++) {
        buf[wid][j0 * P2 + h * 8 + q0] = make_float4(a0[h].x, a0[h].y, b0[h].x, b0[h].y);
        buf[wid][j0 * P2 + h * 8 + q1] = make_float4(a1[h].x, a1[h].y, b1[h].x, b1[h].y);
    }
    __syncwarp();

    // ---- Stage 3: radix-8 over j0; column c' == (h1,h2) reads p = j*65 + c' ----
    #pragma unroll
    for (int j = 0; j < 8; j++) {
        float4 u = buf[wid][j * P2 + c0];
        float4 v = buf[wid][j * P2 + c1];
        a0[j] = make_float2(u.x, u.y);  b0[j] = make_float2(u.z, u.w);
        a1[j] = make_float2(v.x, v.y);  b1[j] = make_float2(v.z, v.w);
    }
    dft8(a0); dft8(b0);
    dft8(a1); dft8(b1);

    // output h = h0*64 + c  (fully coalesced, 256B per warp per store pair)
    if (actA) {
        float2* orow = out + (size_t)rowA * 512;
        #pragma unroll
        for (int h0 = 0; h0 < 8; h0++) {
            orow[h0 * 64 + c0] = a0[h0];
            orow[h0 * 64 + c1] = a1[h0];
        }
    }
    if (actB) {
        float2* orow = out + (size_t)rowB * 512;
        #pragma unroll
        for (int h0 = 0; h0 < 8; h0++) {
            orow[h0 * 64 + c0] = b0[h0];
            orow[h0 * 64 + c1] = b1[h0];
        }
    }
}

extern "C" void kernel_launch(void* const* d_in, const int* in_sizes, int n_in,
                              void* d_out, int out_size)
{
    const float* xre = (const float*)d_in[0];
    const float* xim = (const float*)d_in[1];
    const float* wre = (const float*)d_in[2];
    const float* wim = (const float*)d_in[3];
    float2* out = (float2*)d_out;

    const int nrows = in_sizes[0] / 512;            // 32768
    const int rows_per_cta = WARPS_PER_CTA * 2;     // 8
    const int grid = (nrows + rows_per_cta - 1) / rows_per_cta;   // 4096
    fft512_kernel<<<grid, CTA_THREADS>>>(xre, xim, wre, wim, out, nrows);
}